// round 6
// baseline (speedup 1.0000x reference)
#include <cuda_runtime.h>
#include <cuda.h>
#include <cstdint>

// ============================================================================
// out[m,n] = tanh( sum_k x[m,k] * (exp(s[k]) * V[k,n]) + bias[n] )
// M = 1048576, K = N = 128, fp32 in/out.
//
// sm_103a path: persistent warp-specialized tcgen05 TF32 GEMM (288 thr/CTA):
//   warps 0-3 : epilogue (LDTM + bias + tanh + STG.128)
//   warps 4-7 : A-tile producers (LDG.128 -> cvt.rna.tf32 -> swizzled STS)
//   warp  8   : MMA issuer (16x tcgen05.mma.kind::tf32 SS per 128-row tile)
// compute_103 (portable PTX) stage: smem-tiled FFMA fallback (correct, slow;
// never selected when the sm_103a cubin is present).
// ============================================================================

// tcgen05 is arch-SPECIFIC: only present in the 103a/100a feature set.
#if defined(__CUDA_ARCH__) && !defined(__CUDA_ARCH_FEAT_SM103_ALL) && !defined(__CUDA_ARCH_FEAT_SM100_ALL)
#define RWF_NO_TCGEN05 1
#endif

#define NTHREADS 288
#define SMEM_BYTES 199680
#define IDESC_TF32 0x8200910u   // cF32 | aTF32 | bTF32 | N=128 | M=128

// offsets from 1024-aligned smem base (tcgen05 path)
#define OFF_BIAS 128
#define OFF_SEXP 768
#define OFF_A0   2048
#define OFF_A1   67584
#define OFF_W    133120

// mbarrier offsets (from aligned base)
#define MB_AF0  0
#define MB_AF1  8
#define MB_DF0  16
#define MB_DF1  24
#define MB_DE0  32
#define MB_DE1  40
#define MB_TMEM 48

// ---------------------------------------------------------------------------
// Generic helpers (portable)
// ---------------------------------------------------------------------------
__device__ __forceinline__ uint32_t smem_u32(const void* p) {
    uint32_t a;
    asm("{ .reg .u64 t; cvta.to.shared.u64 t, %1; cvt.u32.u64 %0, t; }"
        : "=r"(a) : "l"(p));
    return a;
}

__device__ __forceinline__ float fast_tanh(float z) {
    // tanh(z) = 1 - 2 / (exp(2z) + 1); exp2-based, saturates correctly at +-inf
    float t, r;
    asm("ex2.approx.f32 %0, %1;" : "=f"(t) : "f"(z * 2.885390081777927f));
    asm("rcp.approx.f32 %0, %1;" : "=f"(r) : "f"(t + 1.0f));
    return fmaf(-2.0f, r, 1.0f);
}

#ifndef RWF_NO_TCGEN05
// ---------------------------------------------------------------------------
// sm_103a-only helpers
// ---------------------------------------------------------------------------
__device__ __forceinline__ uint32_t elect_one() {
    uint32_t r;
    asm volatile("{ .reg .pred p; elect.sync _|p, 0xFFFFFFFF; selp.b32 %0, 1, 0, p; }"
                 : "=r"(r));
    return r;
}

#define MBAR_INIT(addr, cnt) \
    asm volatile("mbarrier.init.shared.b64 [%0], %1;" :: "r"(addr), "r"(cnt) : "memory")

#define MBAR_ARRIVE(addr) \
    asm volatile("mbarrier.arrive.shared.b64 _, [%0];" :: "r"(addr) : "memory")

#define MBAR_WAIT(addr, ph) do {                                              \
    uint32_t _a = (addr), _p = (ph), _d;                                      \
    asm volatile("{\n\t.reg .pred p;\n\t"                                     \
        "mbarrier.try_wait.parity.acquire.cta.shared::cta.b64 p, [%1], %2;\n\t" \
        "selp.b32 %0, 1, 0, p;\n\t}"                                          \
        : "=r"(_d) : "r"(_a), "r"(_p) : "memory");                            \
    while (!_d) {                                                             \
        asm volatile("{\n\t.reg .pred p;\n\t"                                 \
            "mbarrier.try_wait.parity.acquire.cta.shared::cta.b64 p, [%1], %2, 0x989680;\n\t" \
            "selp.b32 %0, 1, 0, p;\n\t}"                                      \
            : "=r"(_d) : "r"(_a), "r"(_p) : "memory");                        \
    }                                                                         \
} while (0)

#define FENCE_ASYNC_SHARED() \
    asm volatile("fence.proxy.async.shared::cta;" ::: "memory")

#define TCG_ALLOC(smem_addr, ncols) \
    asm volatile("tcgen05.alloc.cta_group::1.sync.aligned.shared::cta.b32 [%0], %1;" \
                 :: "r"(smem_addr), "r"(ncols) : "memory")
#define TCG_RELINQ() \
    asm volatile("tcgen05.relinquish_alloc_permit.cta_group::1.sync.aligned;")
#define TCG_DEALLOC(tmem, ncols) \
    asm volatile("tcgen05.dealloc.cta_group::1.sync.aligned.b32 %0, %1;" :: "r"(tmem), "r"(ncols))
#define TCG_COMMIT(mbar) \
    asm volatile("tcgen05.commit.cta_group::1.mbarrier::arrive::one.shared::cluster.b64 [%0];" \
                 :: "r"(mbar) : "memory")
#define TCG_FENCE_BEFORE() asm volatile("tcgen05.fence::before_thread_sync;" ::: "memory")
#define TCG_FENCE_AFTER()  asm volatile("tcgen05.fence::after_thread_sync;" ::: "memory")
#define TCG_WAIT_LD()      asm volatile("tcgen05.wait::ld.sync.aligned;" ::: "memory")

#define TCG_LD_X32(r, tmem_addr)                                              \
    asm volatile("tcgen05.ld.sync.aligned.32x32b.x32.b32 "                    \
        "{%0, %1, %2, %3, %4, %5, %6, %7, "                                   \
        " %8, %9, %10, %11, %12, %13, %14, %15, "                             \
        " %16, %17, %18, %19, %20, %21, %22, %23, "                           \
        " %24, %25, %26, %27, %28, %29, %30, %31}, [%32];"                    \
        : "=r"((r)[0]),  "=r"((r)[1]),  "=r"((r)[2]),  "=r"((r)[3]),          \
          "=r"((r)[4]),  "=r"((r)[5]),  "=r"((r)[6]),  "=r"((r)[7]),          \
          "=r"((r)[8]),  "=r"((r)[9]),  "=r"((r)[10]), "=r"((r)[11]),         \
          "=r"((r)[12]), "=r"((r)[13]), "=r"((r)[14]), "=r"((r)[15]),         \
          "=r"((r)[16]), "=r"((r)[17]), "=r"((r)[18]), "=r"((r)[19]),         \
          "=r"((r)[20]), "=r"((r)[21]), "=r"((r)[22]), "=r"((r)[23]),         \
          "=r"((r)[24]), "=r"((r)[25]), "=r"((r)[26]), "=r"((r)[27]),         \
          "=r"((r)[28]), "=r"((r)[29]), "=r"((r)[30]), "=r"((r)[31])          \
        : "r"(tmem_addr))

// SS-mode tf32 MMA, cta_group::1
__device__ __forceinline__ void mma_tf32_ss(uint32_t d_tmem, uint64_t a_desc,
                                            uint64_t b_desc, uint32_t idesc,
                                            uint32_t enable_d) {
    asm volatile(
        "{\n\t"
        ".reg .pred p;\n\t"
        "setp.ne.u32 p, %5, 0;\n\t"
        "tcgen05.mma.cta_group::1.kind::tf32 [%0], %1, %2, %3, {%4, %4, %4, %4}, p;\n\t"
        "}"
        :: "r"(d_tmem), "l"(a_desc), "l"(b_desc), "r"(idesc), "r"(0u), "r"(enable_d)
        : "memory");
}

// K-major SW128 descriptor (version=1, SBO=64, LBO=1)
__device__ __forceinline__ uint64_t make_desc(uint32_t addr) {
    const uint64_t BASE = (2ull << 61) | (1ull << 46) | (64ull << 32) | (1ull << 16);
    return BASE | ((uint64_t)(addr >> 4) & 0x3FFFull);
}

// blocked-atom SW128 layout for a 128-row x 512-byte tile:
// atom = 8 rows x 128 bytes, 16 atom-rows x 4 atom-cols, atom_off = arow + acol*16
__device__ __forceinline__ uint32_t swz_off(uint32_t row, uint32_t cbyte) {
    uint32_t off = ((row >> 3) + (cbyte >> 7) * 16u) * 1024u
                 + (row & 7u) * 128u + (cbyte & 127u);
    return off ^ ((off >> 3) & 0x70u);
}
#endif  // !RWF_NO_TCGEN05

// ---------------------------------------------------------------------------
// Kernel
// ---------------------------------------------------------------------------
__global__ void __launch_bounds__(NTHREADS, 1)
rwf_tf32_kernel(const float* __restrict__ x, const float* __restrict__ s,
                const float* __restrict__ V, const float* __restrict__ bias,
                float* __restrict__ out, int n_tiles)
{
    extern __shared__ char smem_raw[];

#ifdef RWF_NO_TCGEN05
    // =======================================================================
    // Portable fallback (compute_103 PTX stage): smem-tiled FFMA GEMM.
    // =======================================================================
    float* ws     = (float*)smem_raw;          // [128][129] W' = exp(s)*V
    float* xs     = ws + 128 * 129;            // [128][129] x tile
    float* bias_s = xs + 128 * 129;
    float* sexp_s = bias_s + 128;

    const int tid = threadIdx.x;
    if (tid < 128) {
        sexp_s[tid] = expf(s[tid]);
        bias_s[tid] = bias[tid];
    }
    __syncthreads();
    for (int idx = tid; idx < 128 * 128; idx += NTHREADS) {
        int k = idx >> 7, n = idx & 127;
        ws[k * 129 + n] = sexp_s[k] * V[idx];
    }
    __syncthreads();

    for (int tile = blockIdx.x; tile < n_tiles; tile += gridDim.x) {
        const float* src = x + (size_t)tile * 16384;
        for (int idx = tid; idx < 16384; idx += NTHREADS) {
            int r = idx >> 7, k = idx & 127;
            xs[r * 129 + k] = src[idx];
        }
        __syncthreads();
        if (tid < 256) {
            const int row = tid & 127;
            const int n0  = (tid >> 7) * 64;
            float acc[64];
#pragma unroll
            for (int n = 0; n < 64; n++) acc[n] = bias_s[n0 + n];
            for (int k = 0; k < 128; k++) {
                float xv = xs[row * 129 + k];
#pragma unroll
                for (int n = 0; n < 64; n++)
                    acc[n] = fmaf(xv, ws[k * 129 + n0 + n], acc[n]);
            }
            float* dst = out + ((size_t)tile * 128 + row) * 128 + n0;
#pragma unroll
            for (int n = 0; n < 64; n++) dst[n] = fast_tanh(acc[n]);
        }
        __syncthreads();
    }
#else
    // =======================================================================
    // sm_103a path: warp-specialized tcgen05 TF32 pipeline.
    // =======================================================================
    const uint32_t smem0 = smem_u32(smem_raw);
    const uint32_t base  = (smem0 + 1023u) & ~1023u;
    char* gen = smem_raw + (base - smem0);          // generic pointer at aligned base

    float* bias_s = (float*)(gen + OFF_BIAS);
    float* sexp_s = (float*)(gen + OFF_SEXP);

    const int tid = threadIdx.x;
    const int wid = tid >> 5;

    // ---- prologue -------------------------------------------------------
    if (wid == 8) TCG_ALLOC(base + MB_TMEM, 256);
    if (tid == 0) {
        MBAR_INIT(base + MB_AF0, 128);
        MBAR_INIT(base + MB_AF1, 128);
        MBAR_INIT(base + MB_DF0, 1);
        MBAR_INIT(base + MB_DF1, 1);
        MBAR_INIT(base + MB_DE0, 4);
        MBAR_INIT(base + MB_DE1, 4);
    }
    if (tid < 128) {
        sexp_s[tid] = expf(s[tid]);
        bias_s[tid] = bias[tid];
    }
    __syncthreads();

    uint32_t tmem_base;
    asm volatile("ld.shared.b32 %0, [%1];" : "=r"(tmem_base) : "r"(base + MB_TMEM));

    // Build W' = exp(s)*V, transposed to [N=128 rows, K=128 cols] K-major SW128.
    // B_sm[n, k] = exp(s[k]) * V[k*128 + n]
    for (int idx = tid; idx < 128 * 128; idx += NTHREADS) {
        int k = idx >> 7;
        int n = idx & 127;
        float w = sexp_s[k] * V[idx];
        uint32_t w32;
        asm("cvt.rna.tf32.f32 %0, %1;" : "=r"(w32) : "f"(w));
        uint32_t addr = base + OFF_W + swz_off((uint32_t)n, (uint32_t)k * 4u);
        asm volatile("st.shared.b32 [%0], %1;" :: "r"(addr), "r"(w32) : "memory");
    }
    FENCE_ASYNC_SHARED();
    __syncthreads();

    const int grid = gridDim.x;
    const int bid  = blockIdx.x;

    if (wid >= 4 && wid < 8) {
        // ---------------- producers: fill A tiles -------------------------
        const int ptid = tid - 128;                 // 0..127
        const float4* __restrict__ x4 = (const float4*)x;
        int t = 0;
        for (int tile = bid; tile < n_tiles; tile += grid, ++t) {
            const int sidx = t & 1;
            const int e = t >> 1;
            if (t >= 2) {
                // A[sidx] free once MMA(t-2) committed (d_full completion #e-1)
                MBAR_WAIT(base + MB_DF0 + 8 * sidx, (e + 1) & 1);
            }
            const uint32_t abase = base + (sidx ? OFF_A1 : OFF_A0);
            const float4* src = x4 + (size_t)tile * 4096;
#pragma unroll 8
            for (int i = 0; i < 32; i++) {
                const int f = i * 128 + ptid;       // float4 index within tile
                float4 v = src[f];
                uint32_t row = (uint32_t)f >> 5;
                uint32_t cb  = ((uint32_t)f & 31u) * 16u;
                uint32_t addr = abase + swz_off(row, cb);
                uint32_t a0, a1, a2, a3;
                asm("cvt.rna.tf32.f32 %0, %1;" : "=r"(a0) : "f"(v.x));
                asm("cvt.rna.tf32.f32 %0, %1;" : "=r"(a1) : "f"(v.y));
                asm("cvt.rna.tf32.f32 %0, %1;" : "=r"(a2) : "f"(v.z));
                asm("cvt.rna.tf32.f32 %0, %1;" : "=r"(a3) : "f"(v.w));
                asm volatile("st.shared.v4.b32 [%0], {%1, %2, %3, %4};"
                             :: "r"(addr), "r"(a0), "r"(a1), "r"(a2), "r"(a3) : "memory");
            }
            FENCE_ASYNC_SHARED();
            MBAR_ARRIVE(base + MB_AF0 + 8 * sidx);
        }
    } else if (wid == 8) {
        // ---------------- MMA issuer --------------------------------------
        const uint64_t adesc0 = make_desc(base + OFF_A0);
        const uint64_t adesc1 = make_desc(base + OFF_A1);
        const uint64_t bdesc  = make_desc(base + OFF_W);
        int t = 0;
        for (int tile = bid; tile < n_tiles; tile += grid, ++t) {
            const int sidx = t & 1;
            const int e = t >> 1;
            MBAR_WAIT(base + MB_AF0 + 8 * sidx, e & 1);            // A ready
            if (t >= 2)
                MBAR_WAIT(base + MB_DE0 + 8 * sidx, (e + 1) & 1);  // D drained
            TCG_FENCE_AFTER();
            if (elect_one()) {
                const uint64_t ad = sidx ? adesc1 : adesc0;
                const uint32_t d  = tmem_base + sidx * 128;
#pragma unroll
                for (int k = 0; k < 16; k++) {
                    // k-step: bytes [32k, 32k+32) of the K dimension
                    const uint64_t koff = (uint64_t)((k >> 2) * 1024 + (k & 3) * 2);
                    mma_tf32_ss(d, ad + koff, bdesc + koff, IDESC_TF32, (k > 0) ? 1u : 0u);
                }
                TCG_COMMIT(base + MB_DF0 + 8 * sidx);
            }
        }
    } else {
        // ---------------- epilogue (warps 0-3, 128 threads) ---------------
        float4* __restrict__ out4 = (float4*)out;
        int t = 0;
        for (int tile = bid; tile < n_tiles; tile += grid, ++t) {
            const int sidx = t & 1;
            const int e = t >> 1;
            MBAR_WAIT(base + MB_DF0 + 8 * sidx, e & 1);
            TCG_FENCE_AFTER();
            const uint32_t dt = tmem_base + sidx * 128;
            const size_t grow = (size_t)tile * 128 + (size_t)tid;  // this thread's row
            float4* dst = out4 + grow * 32;
#pragma unroll
            for (int c = 0; c < 4; c++) {
                uint32_t r[32];
                TCG_LD_X32(r, dt + c * 32);
                TCG_WAIT_LD();
#pragma unroll
                for (int j = 0; j < 8; j++) {
                    const int n0 = c * 32 + j * 4;
                    float4 y;
                    y.x = fast_tanh(__uint_as_float(r[j * 4 + 0]) + bias_s[n0 + 0]);
                    y.y = fast_tanh(__uint_as_float(r[j * 4 + 1]) + bias_s[n0 + 1]);
                    y.z = fast_tanh(__uint_as_float(r[j * 4 + 2]) + bias_s[n0 + 2]);
                    y.w = fast_tanh(__uint_as_float(r[j * 4 + 3]) + bias_s[n0 + 3]);
                    dst[c * 8 + j] = y;
                }
            }
            TCG_FENCE_BEFORE();
            if (elect_one()) MBAR_ARRIVE(base + MB_DE0 + 8 * sidx);
        }
    }

    // ---- teardown ---------------------------------------------------------
    __syncthreads();
    if (wid == 8) {
        TCG_RELINQ();
        TCG_DEALLOC(tmem_base, 256);
    }
#endif  // RWF_NO_TCGEN05
}

// ---------------------------------------------------------------------------
// Launch
// ---------------------------------------------------------------------------
extern "C" void kernel_launch(void* const* d_in, const int* in_sizes, int n_in,
                              void* d_out, int out_size)
{
    const float* x    = (const float*)d_in[0];
    const float* s    = (const float*)d_in[1];
    const float* V    = (const float*)d_in[2];
    const float* bias = (const float*)d_in[3];
    float* out = (float*)d_out;

    const long long M = (long long)in_sizes[0] / 128;   // rows of x
    const int n_tiles = (int)(M >> 7);                  // 128-row tiles (8192)

    cudaFuncSetAttribute(rwf_tf32_kernel,
                         cudaFuncAttributeMaxDynamicSharedMemorySize, SMEM_BYTES);

    int sms = 148;
    int dev = 0;
    cudaGetDevice(&dev);
    cudaDeviceGetAttribute(&sms, cudaDevAttrMultiProcessorCount, dev);
    int grid = (sms < n_tiles) ? sms : n_tiles;
    if (grid < 1) grid = 1;

    rwf_tf32_kernel<<<grid, NTHREADS, SMEM_BYTES>>>(x, s, V, bias, out, n_tiles);
}

// round 7
// speedup vs baseline: 1.3423x; 1.3423x over previous
#include <cuda_runtime.h>
#include <cuda.h>
#include <cstdint>

// ============================================================================
// out[m,n] = tanh( sum_k x[m,k] * (exp(s[k]) * V[k,n]) + bias[n] )
// M = 1048576, K = N = 128, fp32 in/out.
//
// sm_103a path: persistent warp-specialized tcgen05 TF32 GEMM (384 thr/CTA):
//   warps 0-7  : epilogue (2x LDTM x32 + bias + tanh.approx + STG.128)
//   warps 8-11 : A producers (cp.async.cg 16B -> swizzled smem, raw fp32;
//                tf32 truncation bias cancelled by scaling W by 1+2^-11)
//   warp  8    : additionally issues 16x tcgen05.mma.kind::tf32 SS per tile
// compute_103 (portable PTX) stage: smem-tiled FFMA fallback (correct, slow;
// never selected when the sm_103a cubin is present).
// ============================================================================

#if defined(__CUDA_ARCH__) && !defined(__CUDA_ARCH_FEAT_SM103_ALL) && !defined(__CUDA_ARCH_FEAT_SM100_ALL)
#define RWF_NO_TCGEN05 1
#endif

#define NTHREADS 384
#define SMEM_BYTES 199680
#define IDESC_TF32 0x8200910u   // cF32 | aTF32 | bTF32 | N=128 | M=128

// offsets from 1024-aligned smem base (tcgen05 path)
#define OFF_BIAS 128
#define OFF_SEXP 768
#define OFF_A0   2048
#define OFF_A1   67584
#define OFF_W    133120

// mbarrier offsets (from aligned base)
#define MB_AF0  0
#define MB_AF1  8
#define MB_DF0  16
#define MB_DF1  24
#define MB_DE0  32
#define MB_DE1  40
#define MB_TMEM 48

// truncation bias compensation: E[trunc rel err] = -2^-11 on A
#define W_BIAS_COMP 1.00048828125f

// ---------------------------------------------------------------------------
// Generic helpers (portable)
// ---------------------------------------------------------------------------
__device__ __forceinline__ uint32_t smem_u32(const void* p) {
    uint32_t a;
    asm("{ .reg .u64 t; cvta.to.shared.u64 t, %1; cvt.u32.u64 %0, t; }"
        : "=r"(a) : "l"(p));
    return a;
}

__device__ __forceinline__ float tanh_fast(float z) {
    float r;
    asm("tanh.approx.f32 %0, %1;" : "=f"(r) : "f"(z));
    return r;
}

#ifndef RWF_NO_TCGEN05
// ---------------------------------------------------------------------------
// sm_103a-only helpers
// ---------------------------------------------------------------------------
__device__ __forceinline__ uint32_t elect_one() {
    uint32_t r;
    asm volatile("{ .reg .pred p; elect.sync _|p, 0xFFFFFFFF; selp.b32 %0, 1, 0, p; }"
                 : "=r"(r));
    return r;
}

#define MBAR_INIT(addr, cnt) \
    asm volatile("mbarrier.init.shared.b64 [%0], %1;" :: "r"(addr), "r"(cnt) : "memory")

#define MBAR_ARRIVE(addr) \
    asm volatile("mbarrier.arrive.shared.b64 _, [%0];" :: "r"(addr) : "memory")

#define MBAR_WAIT(addr, ph) do {                                              \
    uint32_t _a = (addr), _p = (ph), _d;                                      \
    asm volatile("{\n\t.reg .pred p;\n\t"                                     \
        "mbarrier.try_wait.parity.acquire.cta.shared::cta.b64 p, [%1], %2;\n\t" \
        "selp.b32 %0, 1, 0, p;\n\t}"                                          \
        : "=r"(_d) : "r"(_a), "r"(_p) : "memory");                            \
    while (!_d) {                                                             \
        asm volatile("{\n\t.reg .pred p;\n\t"                                 \
            "mbarrier.try_wait.parity.acquire.cta.shared::cta.b64 p, [%1], %2, 0x989680;\n\t" \
            "selp.b32 %0, 1, 0, p;\n\t}"                                      \
            : "=r"(_d) : "r"(_a), "r"(_p) : "memory");                        \
    }                                                                         \
} while (0)

#define FENCE_ASYNC_SHARED() \
    asm volatile("fence.proxy.async.shared::cta;" ::: "memory")

#define CP_ASYNC16(saddr, gptr) \
    asm volatile("cp.async.cg.shared.global [%0], [%1], 16;" \
                 :: "r"(saddr), "l"(gptr) : "memory")
#define CP_COMMIT() asm volatile("cp.async.commit_group;" ::: "memory")
#define CP_WAIT0()  asm volatile("cp.async.wait_group 0;" ::: "memory")

#define TCG_ALLOC(smem_addr, ncols) \
    asm volatile("tcgen05.alloc.cta_group::1.sync.aligned.shared::cta.b32 [%0], %1;" \
                 :: "r"(smem_addr), "r"(ncols) : "memory")
#define TCG_RELINQ() \
    asm volatile("tcgen05.relinquish_alloc_permit.cta_group::1.sync.aligned;")
#define TCG_DEALLOC(tmem, ncols) \
    asm volatile("tcgen05.dealloc.cta_group::1.sync.aligned.b32 %0, %1;" :: "r"(tmem), "r"(ncols))
#define TCG_COMMIT(mbar) \
    asm volatile("tcgen05.commit.cta_group::1.mbarrier::arrive::one.shared::cluster.b64 [%0];" \
                 :: "r"(mbar) : "memory")
#define TCG_FENCE_BEFORE() asm volatile("tcgen05.fence::before_thread_sync;" ::: "memory")
#define TCG_FENCE_AFTER()  asm volatile("tcgen05.fence::after_thread_sync;" ::: "memory")
#define TCG_WAIT_LD()      asm volatile("tcgen05.wait::ld.sync.aligned;" ::: "memory")

#define TCG_LD_X32(r, tmem_addr)                                              \
    asm volatile("tcgen05.ld.sync.aligned.32x32b.x32.b32 "                    \
        "{%0, %1, %2, %3, %4, %5, %6, %7, "                                   \
        " %8, %9, %10, %11, %12, %13, %14, %15, "                             \
        " %16, %17, %18, %19, %20, %21, %22, %23, "                           \
        " %24, %25, %26, %27, %28, %29, %30, %31}, [%32];"                    \
        : "=r"((r)[0]),  "=r"((r)[1]),  "=r"((r)[2]),  "=r"((r)[3]),          \
          "=r"((r)[4]),  "=r"((r)[5]),  "=r"((r)[6]),  "=r"((r)[7]),          \
          "=r"((r)[8]),  "=r"((r)[9]),  "=r"((r)[10]), "=r"((r)[11]),         \
          "=r"((r)[12]), "=r"((r)[13]), "=r"((r)[14]), "=r"((r)[15]),         \
          "=r"((r)[16]), "=r"((r)[17]), "=r"((r)[18]), "=r"((r)[19]),         \
          "=r"((r)[20]), "=r"((r)[21]), "=r"((r)[22]), "=r"((r)[23]),         \
          "=r"((r)[24]), "=r"((r)[25]), "=r"((r)[26]), "=r"((r)[27]),         \
          "=r"((r)[28]), "=r"((r)[29]), "=r"((r)[30]), "=r"((r)[31])          \
        : "r"(tmem_addr))

// SS-mode tf32 MMA, cta_group::1
__device__ __forceinline__ void mma_tf32_ss(uint32_t d_tmem, uint64_t a_desc,
                                            uint64_t b_desc, uint32_t idesc,
                                            uint32_t enable_d) {
    asm volatile(
        "{\n\t"
        ".reg .pred p;\n\t"
        "setp.ne.u32 p, %5, 0;\n\t"
        "tcgen05.mma.cta_group::1.kind::tf32 [%0], %1, %2, %3, {%4, %4, %4, %4}, p;\n\t"
        "}"
        :: "r"(d_tmem), "l"(a_desc), "l"(b_desc), "r"(idesc), "r"(0u), "r"(enable_d)
        : "memory");
}

// K-major SW128 descriptor (version=1, SBO=64, LBO=1)
__device__ __forceinline__ uint64_t make_desc(uint32_t addr) {
    const uint64_t BASE = (2ull << 61) | (1ull << 46) | (64ull << 32) | (1ull << 16);
    return BASE | ((uint64_t)(addr >> 4) & 0x3FFFull);
}

// blocked-atom SW128 layout for a 128-row x 512-byte tile:
// atom = 8 rows x 128 bytes, 16 atom-rows x 4 atom-cols, atom_off = arow + acol*16
__device__ __forceinline__ uint32_t swz_off(uint32_t row, uint32_t cbyte) {
    uint32_t off = ((row >> 3) + (cbyte >> 7) * 16u) * 1024u
                 + (row & 7u) * 128u + (cbyte & 127u);
    return off ^ ((off >> 3) & 0x70u);
}
#endif  // !RWF_NO_TCGEN05

// ---------------------------------------------------------------------------
// Kernel
// ---------------------------------------------------------------------------
__global__ void __launch_bounds__(NTHREADS, 1)
rwf_tf32_kernel(const float* __restrict__ x, const float* __restrict__ s,
                const float* __restrict__ V, const float* __restrict__ bias,
                float* __restrict__ out, int n_tiles)
{
    extern __shared__ char smem_raw[];

#ifdef RWF_NO_TCGEN05
    // =======================================================================
    // Portable fallback (compute_103 PTX stage): smem-tiled FFMA GEMM.
    // =======================================================================
    float* ws     = (float*)smem_raw;          // [128][129] W' = exp(s)*V
    float* xs     = ws + 128 * 129;            // [128][129] x tile
    float* bias_s = xs + 128 * 129;
    float* sexp_s = bias_s + 128;

    const int tid = threadIdx.x;
    if (tid < 128) {
        sexp_s[tid] = expf(s[tid]);
        bias_s[tid] = bias[tid];
    }
    __syncthreads();
    for (int idx = tid; idx < 128 * 128; idx += NTHREADS) {
        int k = idx >> 7, n = idx & 127;
        ws[k * 129 + n] = sexp_s[k] * V[idx];
    }
    __syncthreads();

    for (int tile = blockIdx.x; tile < n_tiles; tile += gridDim.x) {
        const float* src = x + (size_t)tile * 16384;
        for (int idx = tid; idx < 16384; idx += NTHREADS) {
            int r = idx >> 7, k = idx & 127;
            xs[r * 129 + k] = src[idx];
        }
        __syncthreads();
        if (tid < 256) {
            const int row = tid & 127;
            const int n0  = (tid >> 7) * 64;
            float acc[64];
#pragma unroll
            for (int n = 0; n < 64; n++) acc[n] = bias_s[n0 + n];
            for (int k = 0; k < 128; k++) {
                float xv = xs[row * 129 + k];
#pragma unroll
                for (int n = 0; n < 64; n++)
                    acc[n] = fmaf(xv, ws[k * 129 + n0 + n], acc[n]);
            }
            float* dst = out + ((size_t)tile * 128 + row) * 128 + n0;
#pragma unroll
            for (int n = 0; n < 64; n++) dst[n] = tanh_fast(acc[n]);
        }
        __syncthreads();
    }
#else
    // =======================================================================
    // sm_103a path: warp-specialized tcgen05 TF32 pipeline.
    // =======================================================================
    const uint32_t smem0 = smem_u32(smem_raw);
    const uint32_t base  = (smem0 + 1023u) & ~1023u;
    char* gen = smem_raw + (base - smem0);          // generic pointer at aligned base

    float* bias_s = (float*)(gen + OFF_BIAS);
    float* sexp_s = (float*)(gen + OFF_SEXP);

    const int tid = threadIdx.x;
    const int wid = tid >> 5;
    const int lid = tid & 31;

    // ---- prologue -------------------------------------------------------
    if (wid == 8) TCG_ALLOC(base + MB_TMEM, 256);
    if (tid == 0) {
        MBAR_INIT(base + MB_AF0, 128);   // 128 producer threads
        MBAR_INIT(base + MB_AF1, 128);
        MBAR_INIT(base + MB_DF0, 1);     // tcgen05.commit
        MBAR_INIT(base + MB_DF1, 1);
        MBAR_INIT(base + MB_DE0, 8);     // 8 epilogue warps (elected)
        MBAR_INIT(base + MB_DE1, 8);
    }
    if (tid < 128) {
        sexp_s[tid] = expf(s[tid]) * W_BIAS_COMP;   // fold trunc-bias comp into W
        bias_s[tid] = bias[tid];
    }
    __syncthreads();

    uint32_t tmem_base;
    asm volatile("ld.shared.b32 %0, [%1];" : "=r"(tmem_base) : "r"(base + MB_TMEM));

    // Build W' = exp(s)*V*(1+2^-11), transposed to [N rows, K cols] K-major SW128.
    for (int idx = tid; idx < 128 * 128; idx += NTHREADS) {
        int k = idx >> 7;
        int n = idx & 127;
        float w = sexp_s[k] * V[idx];
        uint32_t w32;
        asm("cvt.rna.tf32.f32 %0, %1;" : "=r"(w32) : "f"(w));
        uint32_t addr = base + OFF_W + swz_off((uint32_t)n, (uint32_t)k * 4u);
        asm volatile("st.shared.b32 [%0], %1;" :: "r"(addr), "r"(w32) : "memory");
    }
    FENCE_ASYNC_SHARED();
    __syncthreads();

    const int grid = gridDim.x;
    const int bid  = blockIdx.x;

    if (wid >= 8) {
        // ---------------- producers (warps 8-11; warp 8 also issues MMA) ----
        const int ptid = tid - 256;                 // 0..127
        const float4* __restrict__ x4 = (const float4*)x;
        const uint64_t adesc0 = make_desc(base + OFF_A0);
        const uint64_t adesc1 = make_desc(base + OFF_A1);
        const uint64_t bdesc  = make_desc(base + OFF_W);
        // per-thread constant part of the swizzled address
        const uint32_t cb = ((uint32_t)ptid & 31u) * 16u;
        int t = 0;
        for (int tile = bid; tile < n_tiles; tile += grid, ++t) {
            const int sidx = t & 1;
            const int e = t >> 1;
            if (t >= 2) {
                // A[sidx] reusable once MMA(t-2) committed
                MBAR_WAIT(base + MB_DF0 + 8 * sidx, (e + 1) & 1);
            }
            const uint32_t abase = base + (sidx ? OFF_A1 : OFF_A0);
            const float4* src = x4 + (size_t)tile * 4096;
#pragma unroll
            for (int i = 0; i < 32; i++) {
                const int f = i * 128 + ptid;
                const uint32_t addr = abase + swz_off((uint32_t)f >> 5, cb);
                CP_ASYNC16(addr, src + f);
            }
            CP_COMMIT();
            CP_WAIT0();
            FENCE_ASYNC_SHARED();
            MBAR_ARRIVE(base + MB_AF0 + 8 * sidx);

            if (wid == 8) {
                MBAR_WAIT(base + MB_AF0 + 8 * sidx, e & 1);           // A ready
                if (t >= 2)
                    MBAR_WAIT(base + MB_DE0 + 8 * sidx, (e + 1) & 1); // D drained
                TCG_FENCE_AFTER();
                if (elect_one()) {
                    const uint64_t ad = sidx ? adesc1 : adesc0;
                    const uint32_t d  = tmem_base + sidx * 128;
#pragma unroll
                    for (int k = 0; k < 16; k++) {
                        const uint64_t koff = (uint64_t)((k >> 2) * 1024 + (k & 3) * 2);
                        mma_tf32_ss(d, ad + koff, bdesc + koff, IDESC_TF32,
                                    (k > 0) ? 1u : 0u);
                    }
                    TCG_COMMIT(base + MB_DF0 + 8 * sidx);
                }
            }
        }
    } else {
        // ---------------- epilogue (warps 0-7, 256 threads) ---------------
        const int sp   = wid & 3;        // TMEM subpartition
        const int half = wid >> 2;       // column half (0: cols 0-63, 1: 64-127)
        const int row  = sp * 32 + lid;
        const int colbase = half * 64;
        float4* __restrict__ out4 = (float4*)out;
        int t = 0;
        for (int tile = bid; tile < n_tiles; tile += grid, ++t) {
            const int sidx = t & 1;
            const int e = t >> 1;
            MBAR_WAIT(base + MB_DF0 + 8 * sidx, e & 1);
            TCG_FENCE_AFTER();
            const uint32_t dt = tmem_base + sidx * 128 + colbase;
            uint32_t r[64];
            TCG_LD_X32(r, dt);
            TCG_LD_X32(r + 32, dt + 32);
            TCG_WAIT_LD();
            float4* dst = out4 + ((size_t)tile * 128 + row) * 32 + half * 16;
#pragma unroll
            for (int j = 0; j < 16; j++) {
                const int n0 = colbase + j * 4;
                float4 y;
                y.x = tanh_fast(__uint_as_float(r[j * 4 + 0]) + bias_s[n0 + 0]);
                y.y = tanh_fast(__uint_as_float(r[j * 4 + 1]) + bias_s[n0 + 1]);
                y.z = tanh_fast(__uint_as_float(r[j * 4 + 2]) + bias_s[n0 + 2]);
                y.w = tanh_fast(__uint_as_float(r[j * 4 + 3]) + bias_s[n0 + 3]);
                dst[j] = y;
            }
            TCG_FENCE_BEFORE();
            if (elect_one()) MBAR_ARRIVE(base + MB_DE0 + 8 * sidx);
        }
    }

    // ---- teardown ---------------------------------------------------------
    __syncthreads();
    if (wid == 8) {
        TCG_RELINQ();
        TCG_DEALLOC(tmem_base, 256);
    }
#endif  // RWF_NO_TCGEN05
}

// ---------------------------------------------------------------------------
// Launch
// ---------------------------------------------------------------------------
extern "C" void kernel_launch(void* const* d_in, const int* in_sizes, int n_in,
                              void* d_out, int out_size)
{
    const float* x    = (const float*)d_in[0];
    const float* s    = (const float*)d_in[1];
    const float* V    = (const float*)d_in[2];
    const float* bias = (const float*)d_in[3];
    float* out = (float*)d_out;

    const long long M = (long long)in_sizes[0] / 128;   // rows of x
    const int n_tiles = (int)(M >> 7);                  // 128-row tiles (8192)

    cudaFuncSetAttribute(rwf_tf32_kernel,
                         cudaFuncAttributeMaxDynamicSharedMemorySize, SMEM_BYTES);

    int sms = 148;
    int dev = 0;
    cudaGetDevice(&dev);
    cudaDeviceGetAttribute(&sms, cudaDevAttrMultiProcessorCount, dev);
    int grid = (sms < n_tiles) ? sms : n_tiles;
    if (grid < 1) grid = 1;

    rwf_tf32_kernel<<<grid, NTHREADS, SMEM_BYTES>>>(x, s, V, bias, out, n_tiles);
}

// round 8
// speedup vs baseline: 1.7862x; 1.3306x over previous
#include <cuda_runtime.h>
#include <cuda.h>
#include <cstdint>

// ============================================================================
// out[m,n] = tanh( sum_k x[m,k] * (exp(s[k]) * V[k,n]) + bias[n] )
// M = 1048576, K = N = 128, fp32 in/out.
//
// sm_103a path: persistent warp-specialized tcgen05 TF32 GEMM (384 thr/CTA):
//   warps 0-7  : epilogue (LDTM + bias + tanh.approx + swizzled STS into the
//                freed A buffer + bar.sync + LDS.128 + fully-coalesced STG.128)
//   warps 8-11 : A producers (cp.async.cg 16B -> swizzled smem, raw fp32;
//                tf32 truncation bias cancelled by scaling W by 1+2^-11)
//   warp  8    : additionally issues 16x tcgen05.mma.kind::tf32 SS per tile
// Buffer ring: producer waits DE (epilogue done: A[sidx] was its staging),
// MMA waits AF, epilogue waits DF (tcgen05.commit).
// compute_103 (portable PTX) stage: smem-tiled FFMA fallback.
// ============================================================================

#if defined(__CUDA_ARCH__) && !defined(__CUDA_ARCH_FEAT_SM103_ALL) && !defined(__CUDA_ARCH_FEAT_SM100_ALL)
#define RWF_NO_TCGEN05 1
#endif

#define NTHREADS 384
#define SMEM_BYTES 199680
#define IDESC_TF32 0x8200910u   // cF32 | aTF32 | bTF32 | N=128 | M=128

// offsets from 1024-aligned smem base (tcgen05 path)
#define OFF_BIAS 128
#define OFF_SEXP 768
#define OFF_A0   2048
#define OFF_A1   67584
#define OFF_W    133120

// mbarrier offsets (from aligned base)
#define MB_AF0  0
#define MB_AF1  8
#define MB_DF0  16
#define MB_DF1  24
#define MB_DE0  32
#define MB_DE1  40
#define MB_TMEM 48

// truncation bias compensation: E[trunc rel err] = -2^-11 on A
#define W_BIAS_COMP 1.00048828125f

// ---------------------------------------------------------------------------
// Generic helpers (portable)
// ---------------------------------------------------------------------------
__device__ __forceinline__ uint32_t smem_u32(const void* p) {
    uint32_t a;
    asm("{ .reg .u64 t; cvta.to.shared.u64 t, %1; cvt.u32.u64 %0, t; }"
        : "=r"(a) : "l"(p));
    return a;
}

__device__ __forceinline__ float tanh_fast(float z) {
    float r;
    asm("tanh.approx.f32 %0, %1;" : "=f"(r) : "f"(z));
    return r;
}

#ifndef RWF_NO_TCGEN05
// ---------------------------------------------------------------------------
// sm_103a-only helpers
// ---------------------------------------------------------------------------
__device__ __forceinline__ uint32_t elect_one() {
    uint32_t r;
    asm volatile("{ .reg .pred p; elect.sync _|p, 0xFFFFFFFF; selp.b32 %0, 1, 0, p; }"
                 : "=r"(r));
    return r;
}

#define MBAR_INIT(addr, cnt) \
    asm volatile("mbarrier.init.shared.b64 [%0], %1;" :: "r"(addr), "r"(cnt) : "memory")

#define MBAR_ARRIVE(addr) \
    asm volatile("mbarrier.arrive.shared.b64 _, [%0];" :: "r"(addr) : "memory")

#define MBAR_WAIT(addr, ph) do {                                              \
    uint32_t _a = (addr), _p = (ph), _d;                                      \
    asm volatile("{\n\t.reg .pred p;\n\t"                                     \
        "mbarrier.try_wait.parity.acquire.cta.shared::cta.b64 p, [%1], %2;\n\t" \
        "selp.b32 %0, 1, 0, p;\n\t}"                                          \
        : "=r"(_d) : "r"(_a), "r"(_p) : "memory");                            \
    while (!_d) {                                                             \
        asm volatile("{\n\t.reg .pred p;\n\t"                                 \
            "mbarrier.try_wait.parity.acquire.cta.shared::cta.b64 p, [%1], %2, 0x989680;\n\t" \
            "selp.b32 %0, 1, 0, p;\n\t}"                                      \
            : "=r"(_d) : "r"(_a), "r"(_p) : "memory");                        \
    }                                                                         \
} while (0)

#define FENCE_ASYNC_SHARED() \
    asm volatile("fence.proxy.async.shared::cta;" ::: "memory")

#define CP_ASYNC16(saddr, gptr) \
    asm volatile("cp.async.cg.shared.global [%0], [%1], 16;" \
                 :: "r"(saddr), "l"(gptr) : "memory")
#define CP_COMMIT() asm volatile("cp.async.commit_group;" ::: "memory")
#define CP_WAIT0()  asm volatile("cp.async.wait_group 0;" ::: "memory")

#define TCG_ALLOC(smem_addr, ncols) \
    asm volatile("tcgen05.alloc.cta_group::1.sync.aligned.shared::cta.b32 [%0], %1;" \
                 :: "r"(smem_addr), "r"(ncols) : "memory")
#define TCG_RELINQ() \
    asm volatile("tcgen05.relinquish_alloc_permit.cta_group::1.sync.aligned;")
#define TCG_DEALLOC(tmem, ncols) \
    asm volatile("tcgen05.dealloc.cta_group::1.sync.aligned.b32 %0, %1;" :: "r"(tmem), "r"(ncols))
#define TCG_COMMIT(mbar) \
    asm volatile("tcgen05.commit.cta_group::1.mbarrier::arrive::one.shared::cluster.b64 [%0];" \
                 :: "r"(mbar) : "memory")
#define TCG_FENCE_BEFORE() asm volatile("tcgen05.fence::before_thread_sync;" ::: "memory")
#define TCG_FENCE_AFTER()  asm volatile("tcgen05.fence::after_thread_sync;" ::: "memory")
#define TCG_WAIT_LD()      asm volatile("tcgen05.wait::ld.sync.aligned;" ::: "memory")

#define TCG_LD_X32(r, tmem_addr)                                              \
    asm volatile("tcgen05.ld.sync.aligned.32x32b.x32.b32 "                    \
        "{%0, %1, %2, %3, %4, %5, %6, %7, "                                   \
        " %8, %9, %10, %11, %12, %13, %14, %15, "                             \
        " %16, %17, %18, %19, %20, %21, %22, %23, "                           \
        " %24, %25, %26, %27, %28, %29, %30, %31}, [%32];"                    \
        : "=r"((r)[0]),  "=r"((r)[1]),  "=r"((r)[2]),  "=r"((r)[3]),          \
          "=r"((r)[4]),  "=r"((r)[5]),  "=r"((r)[6]),  "=r"((r)[7]),          \
          "=r"((r)[8]),  "=r"((r)[9]),  "=r"((r)[10]), "=r"((r)[11]),         \
          "=r"((r)[12]), "=r"((r)[13]), "=r"((r)[14]), "=r"((r)[15]),         \
          "=r"((r)[16]), "=r"((r)[17]), "=r"((r)[18]), "=r"((r)[19]),         \
          "=r"((r)[20]), "=r"((r)[21]), "=r"((r)[22]), "=r"((r)[23]),         \
          "=r"((r)[24]), "=r"((r)[25]), "=r"((r)[26]), "=r"((r)[27]),         \
          "=r"((r)[28]), "=r"((r)[29]), "=r"((r)[30]), "=r"((r)[31])          \
        : "r"(tmem_addr))

// SS-mode tf32 MMA, cta_group::1
__device__ __forceinline__ void mma_tf32_ss(uint32_t d_tmem, uint64_t a_desc,
                                            uint64_t b_desc, uint32_t idesc,
                                            uint32_t enable_d) {
    asm volatile(
        "{\n\t"
        ".reg .pred p;\n\t"
        "setp.ne.u32 p, %5, 0;\n\t"
        "tcgen05.mma.cta_group::1.kind::tf32 [%0], %1, %2, %3, {%4, %4, %4, %4}, p;\n\t"
        "}"
        :: "r"(d_tmem), "l"(a_desc), "l"(b_desc), "r"(idesc), "r"(0u), "r"(enable_d)
        : "memory");
}

// K-major SW128 descriptor (version=1, SBO=64, LBO=1)
__device__ __forceinline__ uint64_t make_desc(uint32_t addr) {
    const uint64_t BASE = (2ull << 61) | (1ull << 46) | (64ull << 32) | (1ull << 16);
    return BASE | ((uint64_t)(addr >> 4) & 0x3FFFull);
}

// SW128 xor swizzle within a 1024B atom
__device__ __forceinline__ uint32_t sw128(uint32_t off) {
    return off ^ ((off >> 3) & 0x70u);
}

// blocked-atom SW128 layout for a 128-row x 512-byte tile:
// atom = 8 rows x 128 bytes, 16 atom-rows x 4 atom-cols, atom_off = arow + acol*16
__device__ __forceinline__ uint32_t swz_off(uint32_t row, uint32_t cbyte) {
    uint32_t off = ((row >> 3) + (cbyte >> 7) * 16u) * 1024u
                 + (row & 7u) * 128u + (cbyte & 127u);
    return off ^ ((off >> 3) & 0x70u);
}
#endif  // !RWF_NO_TCGEN05

// ---------------------------------------------------------------------------
// Kernel
// ---------------------------------------------------------------------------
__global__ void __launch_bounds__(NTHREADS, 1)
rwf_tf32_kernel(const float* __restrict__ x, const float* __restrict__ s,
                const float* __restrict__ V, const float* __restrict__ bias,
                float* __restrict__ out, int n_tiles)
{
    extern __shared__ char smem_raw[];

#ifdef RWF_NO_TCGEN05
    // =======================================================================
    // Portable fallback (compute_103 PTX stage): smem-tiled FFMA GEMM.
    // =======================================================================
    float* ws     = (float*)smem_raw;          // [128][129] W' = exp(s)*V
    float* xs     = ws + 128 * 129;            // [128][129] x tile
    float* bias_s = xs + 128 * 129;
    float* sexp_s = bias_s + 128;

    const int tid = threadIdx.x;
    if (tid < 128) {
        sexp_s[tid] = expf(s[tid]);
        bias_s[tid] = bias[tid];
    }
    __syncthreads();
    for (int idx = tid; idx < 128 * 128; idx += NTHREADS) {
        int k = idx >> 7, n = idx & 127;
        ws[k * 129 + n] = sexp_s[k] * V[idx];
    }
    __syncthreads();

    for (int tile = blockIdx.x; tile < n_tiles; tile += gridDim.x) {
        const float* src = x + (size_t)tile * 16384;
        for (int idx = tid; idx < 16384; idx += NTHREADS) {
            int r = idx >> 7, k = idx & 127;
            xs[r * 129 + k] = src[idx];
        }
        __syncthreads();
        if (tid < 256) {
            const int row = tid & 127;
            const int n0  = (tid >> 7) * 64;
            float acc[64];
#pragma unroll
            for (int n = 0; n < 64; n++) acc[n] = bias_s[n0 + n];
            for (int k = 0; k < 128; k++) {
                float xv = xs[row * 129 + k];
#pragma unroll
                for (int n = 0; n < 64; n++)
                    acc[n] = fmaf(xv, ws[k * 129 + n0 + n], acc[n]);
            }
            float* dst = out + ((size_t)tile * 128 + row) * 128 + n0;
#pragma unroll
            for (int n = 0; n < 64; n++) dst[n] = tanh_fast(acc[n]);
        }
        __syncthreads();
    }
#else
    // =======================================================================
    // sm_103a path: warp-specialized tcgen05 TF32 pipeline.
    // =======================================================================
    const uint32_t smem0 = smem_u32(smem_raw);
    const uint32_t base  = (smem0 + 1023u) & ~1023u;
    char* gen = smem_raw + (base - smem0);          // generic pointer at aligned base

    float* bias_s = (float*)(gen + OFF_BIAS);
    float* sexp_s = (float*)(gen + OFF_SEXP);

    const int tid = threadIdx.x;
    const int wid = tid >> 5;
    const int lid = tid & 31;

    // ---- prologue -------------------------------------------------------
    if (wid == 8) TCG_ALLOC(base + MB_TMEM, 256);
    if (tid == 0) {
        MBAR_INIT(base + MB_AF0, 128);   // 128 producer threads
        MBAR_INIT(base + MB_AF1, 128);
        MBAR_INIT(base + MB_DF0, 1);     // tcgen05.commit
        MBAR_INIT(base + MB_DF1, 1);
        MBAR_INIT(base + MB_DE0, 8);     // 8 epilogue warps (elected)
        MBAR_INIT(base + MB_DE1, 8);
    }
    if (tid < 128) {
        sexp_s[tid] = expf(s[tid]) * W_BIAS_COMP;   // fold trunc-bias comp into W
        bias_s[tid] = bias[tid];
    }
    __syncthreads();

    uint32_t tmem_base;
    asm volatile("ld.shared.b32 %0, [%1];" : "=r"(tmem_base) : "r"(base + MB_TMEM));

    // Build W' = exp(s)*V*(1+2^-11), transposed to [N rows, K cols] K-major SW128.
    for (int idx = tid; idx < 128 * 128; idx += NTHREADS) {
        int k = idx >> 7;
        int n = idx & 127;
        float w = sexp_s[k] * V[idx];
        uint32_t w32;
        asm("cvt.rna.tf32.f32 %0, %1;" : "=r"(w32) : "f"(w));
        uint32_t addr = base + OFF_W + swz_off((uint32_t)n, (uint32_t)k * 4u);
        asm volatile("st.shared.b32 [%0], %1;" :: "r"(addr), "r"(w32) : "memory");
    }
    FENCE_ASYNC_SHARED();
    __syncthreads();

    const int grid = gridDim.x;
    const int bid  = blockIdx.x;

    if (wid >= 8) {
        // ---------------- producers (warps 8-11; warp 8 also issues MMA) ----
        const int ptid = tid - 256;                 // 0..127
        const float4* __restrict__ x4 = (const float4*)x;
        const uint64_t adesc0 = make_desc(base + OFF_A0);
        const uint64_t adesc1 = make_desc(base + OFF_A1);
        const uint64_t bdesc  = make_desc(base + OFF_W);
        const uint32_t cb = ((uint32_t)ptid & 31u) * 16u;
        int t = 0;
        for (int tile = bid; tile < n_tiles; tile += grid, ++t) {
            const int sidx = t & 1;
            const int e = t >> 1;
            if (t >= 2) {
                // A[sidx] reusable once epilogue(t-2) finished (it was staging)
                MBAR_WAIT(base + MB_DE0 + 8 * sidx, (e + 1) & 1);
            }
            const uint32_t abase = base + (sidx ? OFF_A1 : OFF_A0);
            const float4* src = x4 + (size_t)tile * 4096;
#pragma unroll
            for (int i = 0; i < 32; i++) {
                const int f = i * 128 + ptid;
                const uint32_t addr = abase + swz_off((uint32_t)f >> 5, cb);
                CP_ASYNC16(addr, src + f);
            }
            CP_COMMIT();
            CP_WAIT0();
            FENCE_ASYNC_SHARED();
            MBAR_ARRIVE(base + MB_AF0 + 8 * sidx);

            if (wid == 8) {
                MBAR_WAIT(base + MB_AF0 + 8 * sidx, e & 1);  // A ready (implies DE chain)
                TCG_FENCE_AFTER();
                if (elect_one()) {
                    const uint64_t ad = sidx ? adesc1 : adesc0;
                    const uint32_t d  = tmem_base + sidx * 128;
#pragma unroll
                    for (int k = 0; k < 16; k++) {
                        const uint64_t koff = (uint64_t)((k >> 2) * 1024 + (k & 3) * 2);
                        mma_tf32_ss(d, ad + koff, bdesc + koff, IDESC_TF32,
                                    (k > 0) ? 1u : 0u);
                    }
                    TCG_COMMIT(base + MB_DF0 + 8 * sidx);
                }
            }
        }
    } else {
        // ---------------- epilogue (warps 0-7, 256 threads) ---------------
        const int sp   = wid & 3;        // TMEM subpartition
        const int half = wid >> 2;       // column half (0: cols 0-63, 1: 64-127)
        const int row  = sp * 32 + lid;
        const int colbase = half * 64;
        float4* __restrict__ out4 = (float4*)out;
        // LDS addressing for the coalesced copy phase (constant per thread)
        const uint32_t ld_chunk = ((uint32_t)lid >> 3) << 14;     // 16KB chunk
        const uint32_t ld_slot  = ((uint32_t)lid & 7u) * 16u;
        int t = 0;
        for (int tile = bid; tile < n_tiles; tile += grid, ++t) {
            const int sidx = t & 1;
            const int e = t >> 1;
            MBAR_WAIT(base + MB_DF0 + 8 * sidx, e & 1);
            TCG_FENCE_AFTER();
            const uint32_t dt = tmem_base + sidx * 128 + colbase;
            uint32_t r[64];
            TCG_LD_X32(r, dt);
            TCG_LD_X32(r + 32, dt + 32);
            TCG_WAIT_LD();
            // stage tanh(acc+bias) into the freed A buffer, SW128-chunked:
            // value(row, c) at stage + (c>>5)*16384 + sw128(row*128 + (c&31)*4)
            const uint32_t stage = base + (sidx ? OFF_A1 : OFF_A0);
            const uint32_t rowoff = (uint32_t)row * 128u;
#pragma unroll
            for (int j = 0; j < 16; j++) {
                const int c  = colbase + j * 4;
                const int n0 = c;
                float y0 = tanh_fast(__uint_as_float(r[j * 4 + 0]) + bias_s[n0 + 0]);
                float y1 = tanh_fast(__uint_as_float(r[j * 4 + 1]) + bias_s[n0 + 1]);
                float y2 = tanh_fast(__uint_as_float(r[j * 4 + 2]) + bias_s[n0 + 2]);
                float y3 = tanh_fast(__uint_as_float(r[j * 4 + 3]) + bias_s[n0 + 3]);
                const uint32_t addr = stage + (((uint32_t)c >> 5) << 14)
                                    + sw128(rowoff + ((uint32_t)c & 31u) * 4u);
                asm volatile("st.shared.v4.b32 [%0], {%1, %2, %3, %4};"
                             :: "r"(addr), "r"(__float_as_uint(y0)),
                                "r"(__float_as_uint(y1)), "r"(__float_as_uint(y2)),
                                "r"(__float_as_uint(y3)) : "memory");
            }
            TCG_FENCE_BEFORE();
            // all 8 epilogue warps' STS visible before the copy phase
            asm volatile("bar.sync 1, 256;" ::: "memory");
            // coalesced copy: warp w writes rows [w*16, w*16+16), one full
            // 512B row per STG wavefront (lane l -> cols 4l..4l+3)
            const size_t gbase = (size_t)tile * 128;
#pragma unroll
            for (int i = 0; i < 16; i++) {
                const uint32_t r2 = (uint32_t)wid * 16 + i;
                const uint32_t addr = stage + ld_chunk + sw128(r2 * 128u + ld_slot);
                uint32_t v0, v1, v2, v3;
                asm volatile("ld.shared.v4.b32 {%0, %1, %2, %3}, [%4];"
                             : "=r"(v0), "=r"(v1), "=r"(v2), "=r"(v3) : "r"(addr));
                float4 y;
                y.x = __uint_as_float(v0); y.y = __uint_as_float(v1);
                y.z = __uint_as_float(v2); y.w = __uint_as_float(v3);
                out4[(gbase + r2) * 32 + (uint32_t)lid] = y;
            }
            FENCE_ASYNC_SHARED();   // order generic LDS before producer's cp.async
            if (elect_one()) MBAR_ARRIVE(base + MB_DE0 + 8 * sidx);
        }
    }

    // ---- teardown ---------------------------------------------------------
    __syncthreads();
    if (wid == 8) {
        TCG_RELINQ();
        TCG_DEALLOC(tmem_base, 256);
    }
#endif  // RWF_NO_TCGEN05
}

// ---------------------------------------------------------------------------
// Launch
// ---------------------------------------------------------------------------
extern "C" void kernel_launch(void* const* d_in, const int* in_sizes, int n_in,
                              void* d_out, int out_size)
{
    const float* x    = (const float*)d_in[0];
    const float* s    = (const float*)d_in[1];
    const float* V    = (const float*)d_in[2];
    const float* bias = (const float*)d_in[3];
    float* out = (float*)d_out;

    const long long M = (long long)in_sizes[0] / 128;   // rows of x
    const int n_tiles = (int)(M >> 7);                  // 128-row tiles (8192)

    cudaFuncSetAttribute(rwf_tf32_kernel,
                         cudaFuncAttributeMaxDynamicSharedMemorySize, SMEM_BYTES);

    int sms = 148;
    int dev = 0;
    cudaGetDevice(&dev);
    cudaDeviceGetAttribute(&sms, cudaDevAttrMultiProcessorCount, dev);
    int grid = (sms < n_tiles) ? sms : n_tiles;
    if (grid < 1) grid = 1;

    rwf_tf32_kernel<<<grid, NTHREADS, SMEM_BYTES>>>(x, s, V, bias, out, n_tiles);
}